// round 3
// baseline (speedup 1.0000x reference)
#include <cuda_runtime.h>

#define B_   4
#define S_   2048
#define H_   16
#define HID_ 2048
#define DK_  128
#define DV_  128
#define P_   (B_*S_)   // 8192 positions

// scratch (allowed: __device__ globals)
__device__ float g_decay[P_*H_];
__device__ float g_beta [P_*H_];

// ============================================================
// Kernel 1: gating GEMM  raw = x @ [Wa;Wb]^T  + epilogue
// ============================================================
#define GT_POS 64
#define GT_K   32

__global__ __launch_bounds__(256) void gate_kernel(
    const float* __restrict__ x,
    const float* __restrict__ Wa, const float* __restrict__ Wb,
    const float* __restrict__ dt_bias, const float* __restrict__ A_log)
{
    __shared__ float xs[GT_POS][GT_K+1];
    __shared__ float ws[32][GT_K+1];
    int t  = threadIdx.x;
    int p0 = blockIdx.x * GT_POS;
    int tx = t & 7;
    int ty = t >> 3;
    float acc[2][4] = {};

    for (int kc = 0; kc < HID_; kc += GT_K) {
        #pragma unroll
        for (int i = 0; i < (GT_POS*GT_K)/256; ++i) {
            int e = i*256 + t; int r = e >> 5, c = e & 31;
            xs[r][c] = x[(size_t)(p0 + r)*HID_ + kc + c];
        }
        #pragma unroll
        for (int i = 0; i < (32*GT_K)/256; ++i) {
            int e = i*256 + t; int f = e >> 5, c = e & 31;
            const float* wrow = (f < 16) ? (Wa + f*HID_) : (Wb + (f-16)*HID_);
            ws[f][c] = wrow[kc + c];
        }
        __syncthreads();
        #pragma unroll
        for (int k = 0; k < GT_K; ++k) {
            float xv0 = xs[2*ty  ][k];
            float xv1 = xs[2*ty+1][k];
            #pragma unroll
            for (int j = 0; j < 4; ++j) {
                float wv = ws[4*tx+j][k];
                acc[0][j] = fmaf(xv0, wv, acc[0][j]);
                acc[1][j] = fmaf(xv1, wv, acc[1][j]);
            }
        }
        __syncthreads();
    }

    #pragma unroll
    for (int i = 0; i < 2; ++i) {
        int p = p0 + 2*ty + i;
        #pragma unroll
        for (int j = 0; j < 4; ++j) {
            int f = 4*tx + j;
            float r = acc[i][j];
            if (f < 16) {
                float z  = r + __ldg(dt_bias + f);
                float sp = fmaxf(z, 0.0f) + log1pf(expf(-fabsf(z)));
                g_decay[p*H_ + f] = expf(-expf(__ldg(A_log + f)) * sp);
            } else {
                g_beta[p*H_ + (f-16)] = r;
            }
        }
    }
}

// ============================================================
// Kernel 2: delta-rule scan, 2-step batched, lk=16 x lv=2.
// Lane (lk = lane&15, lv = lane>>4) owns rows 8*lk..8*lk+8 and
// cols colg*8 + lv*4 .. +4. Raw load slot = 2*lk+lv (16B, rows
// 8*lk+4*lv..+4, distinct & coalesced). Gather = one xor-16
// exchange. State dots reduce over the 16 lk-lanes (xor 1,2,4,8);
// pair dots (on raw data) reduce over all 32 lanes (+ xor 16).
// ============================================================
typedef unsigned long long u64;

__device__ __forceinline__ u64 fma2(u64 a, u64 b, u64 c) {
    u64 d; asm("fma.rn.f32x2 %0, %1, %2, %3;" : "=l"(d) : "l"(a), "l"(b), "l"(c));
    return d;
}
__device__ __forceinline__ u64 mul2(u64 a, u64 b) {
    u64 d; asm("mul.rn.f32x2 %0, %1, %2;" : "=l"(d) : "l"(a), "l"(b));
    return d;
}
__device__ __forceinline__ u64 pack2(float x, float y) {
    u64 d; asm("mov.b64 %0, {%1, %2};" : "=l"(d)
               : "r"(__float_as_uint(x)), "r"(__float_as_uint(y)));
    return d;
}
__device__ __forceinline__ float hadd2(u64 a) {
    unsigned lo, hi;
    asm("mov.b64 {%0, %1}, %2;" : "=r"(lo), "=r"(hi) : "l"(a));
    return __uint_as_float(lo) + __uint_as_float(hi);
}

struct Raw2 {
    u64 k1a, k1b, q1a, q1b;   // step s   raw 16B slices
    u64 k2a, k2b, q2a, q2b;   // step s+1
    float4 v1, v2;
    float g1, b1, g2, b2;
};

__device__ __forceinline__ void load_raw2(Raw2& r,
    const float* kb, const float* qb, const float* vb,
    const float* gb, const float* bb, int s, int slot, int vq)
{
    size_t o1 = (size_t)s * (H_*DK_);
    size_t o2 = o1 + (H_*DK_);
    ulonglong2 t;
    t = __ldg((const ulonglong2*)(kb + o1) + slot); r.k1a = t.x; r.k1b = t.y;
    t = __ldg((const ulonglong2*)(qb + o1) + slot); r.q1a = t.x; r.q1b = t.y;
    t = __ldg((const ulonglong2*)(kb + o2) + slot); r.k2a = t.x; r.k2b = t.y;
    t = __ldg((const ulonglong2*)(qb + o2) + slot); r.q2a = t.x; r.q2b = t.y;
    r.v1 = __ldg((const float4*)(vb + o1) + vq);
    r.v2 = __ldg((const float4*)(vb + o2) + vq);
    size_t gp = (size_t)s * H_;
    r.g1 = __ldg(gb + gp);        r.b1 = __ldg(bb + gp);
    r.g2 = __ldg(gb + gp + H_);   r.b2 = __ldg(bb + gp + H_);
}

__global__ void __launch_bounds__(32) scan_kernel(
    const float* __restrict__ q, const float* __restrict__ k,
    const float* __restrict__ v, float* __restrict__ out)
{
    int bid  = blockIdx.x;
    int colg = bid & 15;          // 16 column groups of 8
    int bh   = bid >> 4;
    int b    = bh >> 4, h = bh & 15;
    int l    = threadIdx.x;
    int lk   = l & 15, lv = l >> 4;
    int slot = 2*lk + lv;         // distinct 16B per lane
    int vq   = colg*2 + lv;       // float4 index (4 cols) in 128-col row

    size_t base = ((size_t)b * S_ * H_ + h) * DK_;
    const float* kb = k + base;
    const float* qb = q + base;
    const float* vb = v + base;
    float*       ob = out + base;
    const float* gb = g_decay + (size_t)b * S_ * H_ + h;
    const float* bb = g_beta  + (size_t)b * S_ * H_ + h;

    // state: st[j][c], j = row-pair 0..3 (8 rows), c = col 0..3
    u64 st[4][4];
    #pragma unroll
    for (int j = 0; j < 4; ++j)
        #pragma unroll
        for (int c = 0; c < 4; ++c) st[j][c] = 0ull;

    const unsigned FM = 0xffffffffu;

    Raw2 cur, nxt;
    load_raw2(cur, kb, qb, vb, gb, bb, 0, slot, vq);

    for (int s = 0; s < S_; s += 2) {
        int sn = (s + 2 < S_) ? s + 2 : S_ - 2;
        load_raw2(nxt, kb, qb, vb, gb, bb, sn, slot, vq);

        // ---- pair dots on raw data (full-warp reduce later) ----
        float a11 = hadd2(fma2(cur.q1b, cur.k1b, mul2(cur.q1a, cur.k1a)));
        float a21 = hadd2(fma2(cur.q2b, cur.k1b, mul2(cur.q2a, cur.k1a)));
        float b21 = hadd2(fma2(cur.k2b, cur.k1b, mul2(cur.k2a, cur.k1a)));
        float a22 = hadd2(fma2(cur.q2b, cur.k2b, mul2(cur.q2a, cur.k2a)));

        // ---- gather: one xor-16 exchange per u64 ----
        u64 k1g[4], q1g[4], k2g[4], q2g[4];
        k1g[0] = cur.k1a; k1g[1] = cur.k1b;
        k1g[2] = __shfl_xor_sync(FM, cur.k1a, 16);
        k1g[3] = __shfl_xor_sync(FM, cur.k1b, 16);
        q1g[0] = cur.q1a; q1g[1] = cur.q1b;
        q1g[2] = __shfl_xor_sync(FM, cur.q1a, 16);
        q1g[3] = __shfl_xor_sync(FM, cur.q1b, 16);
        k2g[0] = cur.k2a; k2g[1] = cur.k2b;
        k2g[2] = __shfl_xor_sync(FM, cur.k2a, 16);
        k2g[3] = __shfl_xor_sync(FM, cur.k2b, 16);
        q2g[0] = cur.q2a; q2g[1] = cur.q2b;
        q2g[2] = __shfl_xor_sync(FM, cur.q2a, 16);
        q2g[3] = __shfl_xor_sync(FM, cur.q2b, 16);

        // ---- state dots: P1,P2,O1,O2 per col ----
        float P1[4], P2[4], O1[4], O2[4];
        #pragma unroll
        for (int c = 0; c < 4; ++c) {
            u64 ap1 = mul2(k1g[0], st[0][c]);
            u64 ap2 = mul2(k2g[0], st[0][c]);
            u64 ao1 = mul2(q1g[0], st[0][c]);
            u64 ao2 = mul2(q2g[0], st[0][c]);
            #pragma unroll
            for (int j = 1; j < 4; ++j) {
                ap1 = fma2(k1g[j], st[j][c], ap1);
                ap2 = fma2(k2g[j], st[j][c], ap2);
                ao1 = fma2(q1g[j], st[j][c], ao1);
                ao2 = fma2(q2g[j], st[j][c], ao2);
            }
            P1[c] = hadd2(ap1); P2[c] = hadd2(ap2);
            O1[c] = hadd2(ao1); O2[c] = hadd2(ao2);
        }

        // ---- one butterfly round for everything ----
        #pragma unroll
        for (int m = 1; m < 16; m <<= 1) {
            #pragma unroll
            for (int c = 0; c < 4; ++c) {
                P1[c] += __shfl_xor_sync(FM, P1[c], m);
                P2[c] += __shfl_xor_sync(FM, P2[c], m);
                O1[c] += __shfl_xor_sync(FM, O1[c], m);
                O2[c] += __shfl_xor_sync(FM, O2[c], m);
            }
            a11 += __shfl_xor_sync(FM, a11, m);
            a21 += __shfl_xor_sync(FM, a21, m);
            b21 += __shfl_xor_sync(FM, b21, m);
            a22 += __shfl_xor_sync(FM, a22, m);
        }
        a11 += __shfl_xor_sync(FM, a11, 16);
        a21 += __shfl_xor_sync(FM, a21, 16);
        b21 += __shfl_xor_sync(FM, b21, 16);
        a22 += __shfl_xor_sync(FM, a22, 16);

        // ---- scalar resolve (per col) ----
        float g1 = cur.g1, be1 = cur.b1, g2 = cur.g2, be2 = cur.b2;
        float g12 = g1 * g2;
        float vv1[4] = {cur.v1.x, cur.v1.y, cur.v1.z, cur.v1.w};
        float vv2[4] = {cur.v2.x, cur.v2.y, cur.v2.z, cur.v2.w};
        float d1[4], d2[4], o1[4], o2[4];
        #pragma unroll
        for (int c = 0; c < 4; ++c) {
            d1[c] = fmaf(-g1, P1[c], vv1[c]) * be1;
            float t = fmaf(b21, d1[c], g1 * P2[c]);
            d2[c] = fmaf(-g2, t, vv2[c]) * be2;
            o1[c] = fmaf(a11, d1[c], g1 * O1[c]);
            o2[c] = fmaf(a22, d2[c], g2 * fmaf(a21, d1[c], g1 * O2[c]));
        }

        // ---- outputs (one writer lane per lv group) ----
        if (lk == 0) {
            size_t w1 = (size_t)s * (H_*DV_);
            ((float4*)(ob + w1))[vq]            = make_float4(o1[0], o1[1], o1[2], o1[3]);
            ((float4*)(ob + w1 + H_*DV_))[vq]   = make_float4(o2[0], o2[1], o2[2], o2[3]);
        }

        // ---- rank-2 state update ----
        u64 g12p = pack2(g12, g12);
        #pragma unroll
        for (int c = 0; c < 4; ++c) {
            u64 e1p = pack2(g2 * d1[c], g2 * d1[c]);
            u64 d2p = pack2(d2[c], d2[c]);
            #pragma unroll
            for (int j = 0; j < 4; ++j) {
                st[j][c] = fma2(k2g[j], d2p,
                           fma2(k1g[j], e1p,
                           mul2(g12p, st[j][c])));
            }
        }

        cur = nxt;
    }
}

// ============================================================
extern "C" void kernel_launch(void* const* d_in, const int* in_sizes, int n_in,
                              void* d_out, int out_size)
{
    (void)in_sizes; (void)n_in; (void)out_size;
    const float* x   = (const float*)d_in[0];
    const float* q   = (const float*)d_in[1];
    const float* k   = (const float*)d_in[2];
    const float* v   = (const float*)d_in[3];
    const float* Wa  = (const float*)d_in[4];
    const float* Wb  = (const float*)d_in[5];
    const float* dtb = (const float*)d_in[6];
    const float* Al  = (const float*)d_in[7];
    float* out = (float*)d_out;

    gate_kernel<<<P_/GT_POS, 256>>>(x, Wa, Wb, dtb, Al);
    scan_kernel<<<B_*H_*(DV_/8), 32>>>(q, k, v, out);
}

// round 5
// speedup vs baseline: 1.2571x; 1.2571x over previous
#include <cuda_runtime.h>

#define B_   4
#define S_   2048
#define H_   16
#define HID_ 2048
#define DK_  128
#define DV_  128
#define P_   (B_*S_)   // 8192 positions

// scratch (allowed: __device__ globals)
__device__ float g_decay[P_*H_];
__device__ float g_beta [P_*H_];

// ============================================================
// Kernel 1: gating GEMM  raw = x @ [Wa;Wb]^T  + epilogue
// ============================================================
#define GT_POS 64
#define GT_K   32

__global__ __launch_bounds__(256) void gate_kernel(
    const float* __restrict__ x,
    const float* __restrict__ Wa, const float* __restrict__ Wb,
    const float* __restrict__ dt_bias, const float* __restrict__ A_log)
{
    __shared__ float xs[GT_POS][GT_K+1];
    __shared__ float ws[32][GT_K+1];
    int t  = threadIdx.x;
    int p0 = blockIdx.x * GT_POS;
    int tx = t & 7;
    int ty = t >> 3;
    float acc[2][4] = {};

    for (int kc = 0; kc < HID_; kc += GT_K) {
        #pragma unroll
        for (int i = 0; i < (GT_POS*GT_K)/256; ++i) {
            int e = i*256 + t; int r = e >> 5, c = e & 31;
            xs[r][c] = x[(size_t)(p0 + r)*HID_ + kc + c];
        }
        #pragma unroll
        for (int i = 0; i < (32*GT_K)/256; ++i) {
            int e = i*256 + t; int f = e >> 5, c = e & 31;
            const float* wrow = (f < 16) ? (Wa + f*HID_) : (Wb + (f-16)*HID_);
            ws[f][c] = wrow[kc + c];
        }
        __syncthreads();
        #pragma unroll
        for (int k = 0; k < GT_K; ++k) {
            float xv0 = xs[2*ty  ][k];
            float xv1 = xs[2*ty+1][k];
            #pragma unroll
            for (int j = 0; j < 4; ++j) {
                float wv = ws[4*tx+j][k];
                acc[0][j] = fmaf(xv0, wv, acc[0][j]);
                acc[1][j] = fmaf(xv1, wv, acc[1][j]);
            }
        }
        __syncthreads();
    }

    #pragma unroll
    for (int i = 0; i < 2; ++i) {
        int p = p0 + 2*ty + i;
        #pragma unroll
        for (int j = 0; j < 4; ++j) {
            int f = 4*tx + j;
            float r = acc[i][j];
            if (f < 16) {
                float z  = r + __ldg(dt_bias + f);
                float sp = fmaxf(z, 0.0f) + log1pf(expf(-fabsf(z)));
                g_decay[p*H_ + f] = expf(-expf(__ldg(A_log + f)) * sp);
            } else {
                g_beta[p*H_ + (f-16)] = r;
            }
        }
    }
}

// ============================================================
// Kernel 2: delta-rule scan. Warp per (b,h, 4 DV cols):
// 2048 warps. lane = (lk = l&7, lv = l>>3). Lane loads the
// DISTINCT coalesced 16B slot = lk*4+lv of k and q; xor8/xor16
// butterfly all-gathers the 8 row-pairs of group lk (ordering
// permutation static & shared by k/q; consumers are sums over j).
// Lane owns column colg*4 + lv.
// Per step: p = k.S[:,col], o = q.S[:,col], qk = q.k (reduced
// over lk lanes xor1,2,4 after hadd);
//   d = (v - g*p)*beta ; S = g*S + k (x) d ; out = g*o + qk*d.
// ============================================================
typedef unsigned long long u64;

__device__ __forceinline__ u64 fma2(u64 a, u64 b, u64 c) {
    u64 d; asm("fma.rn.f32x2 %0, %1, %2, %3;" : "=l"(d) : "l"(a), "l"(b), "l"(c));
    return d;
}
__device__ __forceinline__ u64 mul2(u64 a, u64 b) {
    u64 d; asm("mul.rn.f32x2 %0, %1, %2;" : "=l"(d) : "l"(a), "l"(b));
    return d;
}
__device__ __forceinline__ u64 pack2(float x, float y) {
    u64 d; asm("mov.b64 %0, {%1, %2};" : "=l"(d)
               : "r"(__float_as_uint(x)), "r"(__float_as_uint(y)));
    return d;
}
__device__ __forceinline__ float hadd2(u64 a) {
    unsigned lo, hi;
    asm("mov.b64 {%0, %1}, %2;" : "=r"(lo), "=r"(hi) : "l"(a));
    return __uint_as_float(lo) + __uint_as_float(hi);
}

struct Raw  { u64 kx, ky, qx, qy; float v, g, b; };
struct Gath { u64 k2[8], q2[8]; float v, g, b; };

__device__ __forceinline__ void load_raw(Raw& r,
    const float* kb, const float* qb, const float* vb,
    const float* gb, const float* bb, int s, int slot, int col)
{
    size_t off = (size_t)s * (H_*DK_);
    ulonglong2 kk = __ldg((const ulonglong2*)(kb + off) + slot);
    r.kx = kk.x; r.ky = kk.y;
    ulonglong2 qq = __ldg((const ulonglong2*)(qb + off) + slot);
    r.qx = qq.x; r.qy = qq.y;
    r.v = __ldg(vb + off + col);
    r.g = __ldg(gb + (size_t)s*H_);
    r.b = __ldg(bb + (size_t)s*H_);
}

__device__ __forceinline__ void gather(Gath& g, const Raw& r)
{
    const unsigned m = 0xffffffffu;
    g.k2[0] = r.kx;
    g.k2[1] = r.ky;
    g.k2[2] = __shfl_xor_sync(m, r.kx, 8);
    g.k2[3] = __shfl_xor_sync(m, r.ky, 8);
    g.k2[4] = __shfl_xor_sync(m, g.k2[0], 16);
    g.k2[5] = __shfl_xor_sync(m, g.k2[1], 16);
    g.k2[6] = __shfl_xor_sync(m, g.k2[2], 16);
    g.k2[7] = __shfl_xor_sync(m, g.k2[3], 16);
    g.q2[0] = r.qx;
    g.q2[1] = r.qy;
    g.q2[2] = __shfl_xor_sync(m, r.qx, 8);
    g.q2[3] = __shfl_xor_sync(m, r.qy, 8);
    g.q2[4] = __shfl_xor_sync(m, g.q2[0], 16);
    g.q2[5] = __shfl_xor_sync(m, g.q2[1], 16);
    g.q2[6] = __shfl_xor_sync(m, g.q2[2], 16);
    g.q2[7] = __shfl_xor_sync(m, g.q2[3], 16);
    g.v = r.v; g.g = r.g; g.b = r.b;
}

__device__ __forceinline__ void do_step(const Gath& c, u64 st[8],
                                        float* outp, int lk, int col)
{
    u64 p2 = 0, o2 = 0, qk2 = 0;
    #pragma unroll
    for (int j = 0; j < 8; ++j) {
        p2  = fma2(c.k2[j], st[j], p2);
        o2  = fma2(c.q2[j], st[j], o2);
        qk2 = fma2(c.q2[j], c.k2[j], qk2);
    }
    float p  = hadd2(p2);
    float o  = hadd2(o2);
    float qk = hadd2(qk2);
    #pragma unroll
    for (int m = 1; m < 8; m <<= 1) {
        p  += __shfl_xor_sync(0xffffffffu, p, m);
        o  += __shfl_xor_sync(0xffffffffu, o, m);
        qk += __shfl_xor_sync(0xffffffffu, qk, m);
    }
    float g = c.g, be = c.b;
    float d = fmaf(-g, p, c.v) * be;
    u64 g2 = pack2(g, g), d2 = pack2(d, d);
    #pragma unroll
    for (int j = 0; j < 8; ++j)
        st[j] = fma2(c.k2[j], d2, mul2(g2, st[j]));
    if (lk == 0)
        outp[col] = fmaf(g, o, qk*d);
}

__global__ void __launch_bounds__(32) scan_kernel(
    const float* __restrict__ q, const float* __restrict__ k,
    const float* __restrict__ v, float* __restrict__ out)
{
    int bid  = blockIdx.x;
    int colg = bid & 31;          // 32 column groups of 4
    int bh   = bid >> 5;
    int b    = bh >> 4, h = bh & 15;
    int l    = threadIdx.x;
    int lk   = l & 7, lv = l >> 3;
    int slot = lk*4 + lv;         // distinct 16B per lane, coalesced
    int col  = colg*4 + lv;       // this lane's DV column

    size_t base = ((size_t)b * S_ * H_ + h) * DK_;
    const float* kb = k + base;
    const float* qb = q + base;
    const float* vb = v + base;
    float*       ob = out + base;
    const float* gb = g_decay + (size_t)b * S_ * H_ + h;
    const float* bb = g_beta  + (size_t)b * S_ * H_ + h;

    u64 st[8];
    #pragma unroll
    for (int j = 0; j < 8; ++j) st[j] = 0ull;

    // pipeline: ldg(s+2) -> gather(s+1) -> compute(s)
    Raw r0, r1, rt;
    Gath gA, gB;
    load_raw(r0, kb, qb, vb, gb, bb, 0, slot, col);
    load_raw(r1, kb, qb, vb, gb, bb, 1, slot, col);
    gather(gA, r0);

    for (int s = 0; s < S_; s += 2) {
        int i2 = (s+2 < S_) ? s+2 : S_-1;
        int i3 = (s+3 < S_) ? s+3 : S_-1;
        load_raw(rt, kb, qb, vb, gb, bb, i2, slot, col);
        gather(gB, r1);                               // r1 loaded one iter ago
        do_step(gA, st, ob + (size_t)s*(H_*DV_), lk, col);
        load_raw(r1, kb, qb, vb, gb, bb, i3, slot, col);
        gather(gA, rt);                               // rt loaded ~1 step ago
        do_step(gB, st, ob + (size_t)(s+1)*(H_*DV_), lk, col);
        r0 = rt;
    }
}

// ============================================================
extern "C" void kernel_launch(void* const* d_in, const int* in_sizes, int n_in,
                              void* d_out, int out_size)
{
    (void)in_sizes; (void)n_in; (void)out_size;
    const float* x   = (const float*)d_in[0];
    const float* q   = (const float*)d_in[1];
    const float* k   = (const float*)d_in[2];
    const float* v   = (const float*)d_in[3];
    const float* Wa  = (const float*)d_in[4];
    const float* Wb  = (const float*)d_in[5];
    const float* dtb = (const float*)d_in[6];
    const float* Al  = (const float*)d_in[7];
    float* out = (float*)d_out;

    gate_kernel<<<P_/GT_POS, 256>>>(x, Wa, Wb, dtb, Al);
    scan_kernel<<<B_*H_*(DV_/4), 32>>>(q, k, v, out);
}